// round 12
// baseline (speedup 1.0000x reference)
#include <cuda_runtime.h>
#include <cuda_bf16.h>
#include <cstdint>

#define N_TRAIN 8192
#define M_PTS   8192
#define D_DIM   256
#define S_SPLIT 8
#define ROWS_PER_SPLIT (N_TRAIN / S_SPLIT)   // 1024
#define BM 128
#define BN 128
#define NCOLS (M_PTS / BN)                   // 64
#define ITERS (ROWS_PER_SPLIT / BM)          // 8
#define NTHREADS 256

#define KC (1.4426950408889634f / 1024.0f)   // (1/sigma)^2 * log2(e)

// SMEM (bytes). int8 tiles: row = 256B, 16B chunks XOR-swizzled (ch ^ (row&7)).
#define OFF_B   0            // x tile (resident)        32KB
#define OFF_A0  32768        // x_train stage 0          32KB
#define OFF_A1  65536        // x_train stage 1          32KB
#define OFF_RED 98304        // cross-warp reduce         1KB
#define SMEM_REQ 99328

__device__ char   g_Aq[(size_t)N_TRAIN * D_DIM];   // x_train int8
__device__ char   g_Bq[(size_t)M_PTS * D_DIM];     // x int8
__device__ float4 g_wn2[N_TRAIN];                  // {alpha*y, KC*s^2*sumq2, 2*KC*s, 0}
__device__ float2 g_km2[M_PTS];                    // {KC*s^2*sumq2, s}
__device__ float  g_part[S_SPLIT][M_PTS];
__device__ unsigned g_tick[NCOLS];                 // finalization tickets

// ---------------------------------------------------------------- helpers
__device__ __forceinline__ uint32_t smem_u32(const void* p) {
    uint32_t a;
    asm("{ .reg .u64 t; cvta.to.shared.u64 t, %1; cvt.u32.u64 %0, t; }"
        : "=r"(a) : "l"(p));
    return a;
}

__device__ __forceinline__ void imma16832(int* c, const uint32_t* a,
                                          uint32_t b0, uint32_t b1) {
    asm volatile(
        "mma.sync.aligned.m16n8k32.row.col.s32.s8.s8.s32 "
        "{%0,%1,%2,%3}, {%4,%5,%6,%7}, {%8,%9}, {%0,%1,%2,%3};\n"
        : "+r"(c[0]), "+r"(c[1]), "+r"(c[2]), "+r"(c[3])
        : "r"(a[0]), "r"(a[1]), "r"(a[2]), "r"(a[3]), "r"(b0), "r"(b1));
}

#define LDSM_X4(r0, r1, r2, r3, addr)                                        \
    asm volatile("ldmatrix.sync.aligned.m8n8.x4.shared.b16 {%0,%1,%2,%3}, [%4];" \
                 : "=r"(r0), "=r"(r1), "=r"(r2), "=r"(r3) : "r"(addr))

// 128 x 256 int8 tile (32KB) -> swizzled SMEM via cp.async (256 threads)
__device__ __forceinline__ void cp_tile(uint32_t dst, const char* src, int tid) {
#pragma unroll
    for (int j = 0; j < 8; j++) {
        int idx = tid + j * NTHREADS;                 // 0..2047 16B chunks
        int row = idx >> 4;                           // 16 chunks per 256B row
        int ch  = idx & 15;
        uint32_t so = dst + (uint32_t)row * 256 + (uint32_t)((ch ^ (row & 7)) << 4);
        asm volatile("cp.async.cg.shared.global [%0], [%1], 16;"
                     :: "r"(so), "l"(src + (size_t)idx * 16) : "memory");
    }
}

// ---------------------------------------------------------------- prep
// per-row symmetric int8 quantization: s = rowmax/127, q = rn(x*127/rowmax).
// 4 rows per warp with all 8 global loads batched up-front (MLP 8).
__global__ void __launch_bounds__(256) prep_kernel(const float* __restrict__ xt,
                                                   const float* __restrict__ yt,
                                                   const float* __restrict__ al,
                                                   const float* __restrict__ x) {
    if (blockIdx.x == 0 && threadIdx.x < NCOLS) g_tick[threadIdx.x] = 0u;

    int w0   = blockIdx.x * 32 + (threadIdx.x >> 5) * 4;
    int lane = threadIdx.x & 31;

    float4 v[4][2];
    const float* srcs[4];
    char* dsts[4];
#pragma unroll
    for (int rr = 0; rr < 4; rr++) {
        int w = w0 + rr;
        bool isA = (w < N_TRAIN);
        srcs[rr] = isA ? xt + (size_t)w * D_DIM
                       : x + (size_t)(w - N_TRAIN) * D_DIM;
        dsts[rr] = isA ? g_Aq + (size_t)w * D_DIM
                       : g_Bq + (size_t)(w - N_TRAIN) * D_DIM;
    }
    // issue all 8 loads before any consumption (MLP 8)
#pragma unroll
    for (int rr = 0; rr < 4; rr++) {
        v[rr][0] = ((const float4*)srcs[rr])[lane];
        v[rr][1] = ((const float4*)srcs[rr])[lane + 32];
    }

#pragma unroll
    for (int rr = 0; rr < 4; rr++) {
        int w = w0 + rr;
        bool isA = (w < N_TRAIN);
        float4 v0 = v[rr][0], v1 = v[rr][1];

        float am = fmaxf(fmaxf(fabsf(v0.x), fabsf(v0.y)), fmaxf(fabsf(v0.z), fabsf(v0.w)));
        am = fmaxf(am, fmaxf(fmaxf(fabsf(v1.x), fabsf(v1.y)), fmaxf(fabsf(v1.z), fabsf(v1.w))));
#pragma unroll
        for (int o = 16; o > 0; o >>= 1) am = fmaxf(am, __shfl_xor_sync(0xffffffffu, am, o));

        bool ok = (am > 1e-30f);
        float r = ok ? (127.0f / am) : 0.f;
        float s = ok ? (am * (1.0f / 127.0f)) : 0.f;

        int q0 = __float2int_rn(v0.x * r), q1 = __float2int_rn(v0.y * r);
        int q2 = __float2int_rn(v0.z * r), q3 = __float2int_rn(v0.w * r);
        int q4 = __float2int_rn(v1.x * r), q5 = __float2int_rn(v1.y * r);
        int q6 = __float2int_rn(v1.z * r), q7 = __float2int_rn(v1.w * r);

        int sq = q0*q0 + q1*q1 + q2*q2 + q3*q3 + q4*q4 + q5*q5 + q6*q6 + q7*q7;
#pragma unroll
        for (int o = 16; o > 0; o >>= 1) sq += __shfl_xor_sync(0xffffffffu, sq, o);

        uint32_t p0 = (q0 & 255) | ((q1 & 255) << 8) | ((q2 & 255) << 16) | ((uint32_t)(q3 & 255) << 24);
        uint32_t p1 = (q4 & 255) | ((q5 & 255) << 8) | ((q6 & 255) << 16) | ((uint32_t)(q7 & 255) << 24);
        ((uint32_t*)dsts[rr])[lane]      = p0;
        ((uint32_t*)dsts[rr])[lane + 32] = p1;

        if (lane == 0) {
            float n2 = KC * s * s * (float)sq;
            if (isA) g_wn2[w] = make_float4(al[w] * yt[w], n2, 2.0f * KC * s, 0.f);
            else     g_km2[w - N_TRAIN] = make_float2(n2, s);
        }
    }
}

// ---------------------------------------------------------------- main
extern "C" __global__ void __launch_bounds__(NTHREADS, 2)
svm_main_kernel(float* __restrict__ out) {
    extern __shared__ char smem_raw[];
    const uint32_t s_base = smem_u32(smem_raw);
    const uint32_t sB_u   = s_base + OFF_B;
    const uint32_t sA_u[2] = { s_base + OFF_A0, s_base + OFF_A1 };
    float* sRed = (float*)(smem_raw + OFF_RED);
    __shared__ unsigned sLast;

    const int tid  = threadIdx.x;
    const int lane = tid & 31;
    const int wid  = tid >> 5;
    const int wr   = wid >> 2;     // 0..1 : 64-row band
    const int wc   = wid & 3;      // 0..3 : 32-col band
    const int m0   = blockIdx.x * BN;
    const int n0   = blockIdx.y * ROWS_PER_SPLIT;

    // prologue: resident B + A stage 0
    cp_tile(sB_u, g_Bq + (size_t)m0 * D_DIM, tid);
    cp_tile(sA_u[0], g_Aq + (size_t)n0 * D_DIM, tid);
    asm volatile("cp.async.commit_group;");
    asm volatile("cp.async.wait_group 0;");
    __syncthreads();

    // ldmatrix per-lane bases (256B rows)
    const uint32_t aro  = (uint32_t)(wr * 64 + (lane & 15)) * 256;
    const uint32_t bro  = (uint32_t)(wc * 32 + (lane & 15)) * 256;
    const uint32_t csel = (uint32_t)(lane >> 4) & 1u;
    const uint32_t xr7  = (uint32_t)(lane & 7);
    const uint32_t bB   = sB_u + bro;

    const int colbase = m0 + wc * 32 + (lane & 3) * 2;   // j -> colbase + (j>>1)*8 + (j&1)

    float colacc[8];
#pragma unroll
    for (int j = 0; j < 8; j++) colacc[j] = 0.f;

    for (int i = 0; i < ITERS; i++) {
        const int s = i & 1;

        if (i + 1 < ITERS)
            cp_tile(sA_u[s ^ 1], g_Aq + (size_t)(n0 + (i + 1) * BM) * D_DIM, tid);
        asm volatile("cp.async.commit_group;");

        // ---- IMMA: 128x128x256 int8 tile ----
        int acc[4][4][4];
#pragma unroll
        for (int mf = 0; mf < 4; mf++)
#pragma unroll
            for (int ng = 0; ng < 4; ng++)
#pragma unroll
                for (int q = 0; q < 4; q++) acc[mf][ng][q] = 0;

        const uint32_t aB = sA_u[s] + aro;
#pragma unroll
        for (int ks = 0; ks < 8; ks++) {
            const uint32_t coff = (((2u * ks + csel) ^ xr7) << 4);
            uint32_t a[4][4], bq[2][4];
#pragma unroll
            for (int mf = 0; mf < 4; mf++)
                LDSM_X4(a[mf][0], a[mf][1], a[mf][2], a[mf][3], aB + mf * 4096 + coff);
#pragma unroll
            for (int p = 0; p < 2; p++)
                LDSM_X4(bq[p][0], bq[p][1], bq[p][2], bq[p][3], bB + p * 4096 + coff);
#pragma unroll
            for (int mf = 0; mf < 4; mf++)
#pragma unroll
                for (int ng = 0; ng < 4; ng++)
                    imma16832(acc[mf][ng], a[mf],
                              bq[ng >> 1][ng & 1], bq[ng >> 1][(ng & 1) + 2]);
        }

        // ---- epilogue: dequant + exp + weighted accumulate ----
#pragma unroll
        for (int mf = 0; mf < 4; mf++)
#pragma unroll
            for (int rh = 0; rh < 2; rh++) {
                float4 wn = __ldg(&g_wn2[n0 + i * BM + wr * 64 + mf * 16 + rh * 8 + (lane >> 2)]);
                const float negn = -wn.y;
#pragma unroll
                for (int ng = 0; ng < 4; ng++)
#pragma unroll
                    for (int h = 0; h < 2; h++) {
                        float2 cm = __ldg(&g_km2[colbase + ng * 8 + h]);
                        float df = (float)acc[mf][ng][rh * 2 + h];
                        float coef = wn.z * cm.y;            // 2*KC*s_a*s_b
                        float arg = fmaf(df, coef, negn) - cm.x;
                        arg = fminf(arg, 0.f);
                        float ev;
                        asm("ex2.approx.ftz.f32 %0, %1;" : "=f"(ev) : "f"(arg));
                        colacc[ng * 2 + h] = fmaf(ev, wn.x, colacc[ng * 2 + h]);
                    }
            }

        asm volatile("cp.async.wait_group 0;");
        __syncthreads();
    }

    // ---- deterministic column reduction ----
#pragma unroll
    for (int j = 0; j < 8; j++) {
        float v = colacc[j];
        v += __shfl_xor_sync(0xffffffffu, v, 4);
        v += __shfl_xor_sync(0xffffffffu, v, 8);
        v += __shfl_xor_sync(0xffffffffu, v, 16);
        colacc[j] = v;
    }
    if (lane < 4) {
#pragma unroll
        for (int j = 0; j < 8; j++) {
            int c = wc * 32 + (j >> 1) * 8 + lane * 2 + (j & 1);
            sRed[wr * BN + c] = colacc[j];
        }
    }
    __syncthreads();
    if (tid < BN)
        g_part[blockIdx.y][m0 + tid] = sRed[tid] + sRed[BN + tid];
    __syncthreads();   // all partial stores done before the ticket

    // ---- fused finalization: last split-CTA for this column tile sums ----
    if (tid == 0) {
        __threadfence();
        sLast = atomicAdd(&g_tick[blockIdx.x], 1u);
    }
    __syncthreads();
    if (sLast == S_SPLIT - 1) {
        __threadfence();                 // acquire side
        if (tid < BN) {
            const volatile float* gp = &g_part[0][m0 + tid];
            float ssum = 0.f;
#pragma unroll
            for (int r = 0; r < S_SPLIT; r++)
                ssum += gp[(size_t)r * M_PTS];   // fixed order r=0..7 -> deterministic
            out[m0 + tid] = ssum;
        }
    }
}

// ---------------------------------------------------------------- launch
extern "C" void kernel_launch(void* const* d_in, const int* in_sizes, int n_in,
                              void* d_out, int out_size) {
    const float* xt = (const float*)d_in[0];
    const float* yt = (const float*)d_in[1];
    const float* al = (const float*)d_in[2];
    const float* x  = (const float*)d_in[3];

    cudaFuncSetAttribute(svm_main_kernel,
                         cudaFuncAttributeMaxDynamicSharedMemorySize, SMEM_REQ);

    prep_kernel<<<(N_TRAIN + M_PTS) / 32, 256>>>(xt, yt, al, x);
    svm_main_kernel<<<dim3(NCOLS, S_SPLIT), NTHREADS, SMEM_REQ>>>((float*)d_out);
}

// round 13
// speedup vs baseline: 1.1223x; 1.1223x over previous
#include <cuda_runtime.h>
#include <cuda_bf16.h>
#include <cstdint>

#define N_TRAIN 8192
#define M_PTS   8192
#define D_DIM   256
#define S_SPLIT 16
#define ROWS_PER_SPLIT (N_TRAIN / S_SPLIT)   // 512
#define BM 64            // x_train rows per iteration
#define BN 128           // x points per CTA (output cols)
#define ITERS (ROWS_PER_SPLIT / BM)          // 8
#define NTHREADS 256

#define KC (1.4426950408889634f / 1024.0f)   // (1/sigma)^2 * log2(e)

// SMEM (bytes). int8 tiles: row = 256B, 16B chunks XOR-swizzled (ch ^ (row&7)).
#define OFF_B   0            // x tile (resident)        32KB
#define OFF_A0  32768        // x_train stage 0          16KB
#define OFF_A1  49152        // x_train stage 1          16KB
#define OFF_RED 65536        // cross-warp reduce         1KB
#define SMEM_REQ 66560

__device__ char   g_Aq[(size_t)N_TRAIN * D_DIM];   // x_train int8
__device__ char   g_Bq[(size_t)M_PTS * D_DIM];     // x int8
__device__ float4 g_wn2[N_TRAIN];                  // {alpha*y, KC*s^2*sumq2, 2*KC*s, 0}
__device__ float2 g_km2[M_PTS];                    // {KC*s^2*sumq2, s}
__device__ float  g_part[S_SPLIT][M_PTS];

// ---------------------------------------------------------------- helpers
__device__ __forceinline__ uint32_t smem_u32(const void* p) {
    uint32_t a;
    asm("{ .reg .u64 t; cvta.to.shared.u64 t, %1; cvt.u32.u64 %0, t; }"
        : "=r"(a) : "l"(p));
    return a;
}

__device__ __forceinline__ void imma16832(int* c, const uint32_t* a,
                                          uint32_t b0, uint32_t b1) {
    asm volatile(
        "mma.sync.aligned.m16n8k32.row.col.s32.s8.s8.s32 "
        "{%0,%1,%2,%3}, {%4,%5,%6,%7}, {%8,%9}, {%0,%1,%2,%3};\n"
        : "+r"(c[0]), "+r"(c[1]), "+r"(c[2]), "+r"(c[3])
        : "r"(a[0]), "r"(a[1]), "r"(a[2]), "r"(a[3]), "r"(b0), "r"(b1));
}

#define LDSM_X4(r0, r1, r2, r3, addr)                                        \
    asm volatile("ldmatrix.sync.aligned.m8n8.x4.shared.b16 {%0,%1,%2,%3}, [%4];" \
                 : "=r"(r0), "=r"(r1), "=r"(r2), "=r"(r3) : "r"(addr))

// ROWS x 256 int8 tile -> swizzled SMEM via cp.async (256 threads)
template <int ROWS>
__device__ __forceinline__ void cp_tile(uint32_t dst, const char* src, int tid) {
#pragma unroll
    for (int j = 0; j < (ROWS * 16) / NTHREADS; j++) {
        int idx = tid + j * NTHREADS;                 // 16B chunks
        int row = idx >> 4;                           // 16 chunks per 256B row
        int ch  = idx & 15;
        uint32_t so = dst + (uint32_t)row * 256 + (uint32_t)((ch ^ (row & 7)) << 4);
        asm volatile("cp.async.cg.shared.global [%0], [%1], 16;"
                     :: "r"(so), "l"(src + (size_t)idx * 16) : "memory");
    }
}

// ---------------------------------------------------------------- prep
// per-row symmetric int8 quantization: s = rowmax/127, q = rn(x*127/rowmax).
// 2 rows per warp, 16 rows per block.  (R11 version, measured 7.1us)
__global__ void __launch_bounds__(256) prep_kernel(const float* __restrict__ xt,
                                                   const float* __restrict__ yt,
                                                   const float* __restrict__ al,
                                                   const float* __restrict__ x) {
    int w0   = blockIdx.x * 16 + (threadIdx.x >> 5) * 2;
    int lane = threadIdx.x & 31;

#pragma unroll
    for (int rr = 0; rr < 2; rr++) {
        int w = w0 + rr;
        bool isA = (w < N_TRAIN);
        const float* src = isA ? xt + (size_t)w * D_DIM
                               : x + (size_t)(w - N_TRAIN) * D_DIM;
        char* dst = isA ? g_Aq + (size_t)w * D_DIM
                        : g_Bq + (size_t)(w - N_TRAIN) * D_DIM;

        float4 v0 = ((const float4*)src)[lane];
        float4 v1 = ((const float4*)src)[lane + 32];

        float am = fmaxf(fmaxf(fabsf(v0.x), fabsf(v0.y)), fmaxf(fabsf(v0.z), fabsf(v0.w)));
        am = fmaxf(am, fmaxf(fmaxf(fabsf(v1.x), fabsf(v1.y)), fmaxf(fabsf(v1.z), fabsf(v1.w))));
#pragma unroll
        for (int o = 16; o > 0; o >>= 1) am = fmaxf(am, __shfl_xor_sync(0xffffffffu, am, o));

        bool ok = (am > 1e-30f);
        float r = ok ? (127.0f / am) : 0.f;
        float s = ok ? (am * (1.0f / 127.0f)) : 0.f;

        int q0 = __float2int_rn(v0.x * r), q1 = __float2int_rn(v0.y * r);
        int q2 = __float2int_rn(v0.z * r), q3 = __float2int_rn(v0.w * r);
        int q4 = __float2int_rn(v1.x * r), q5 = __float2int_rn(v1.y * r);
        int q6 = __float2int_rn(v1.z * r), q7 = __float2int_rn(v1.w * r);

        int sq = q0*q0 + q1*q1 + q2*q2 + q3*q3 + q4*q4 + q5*q5 + q6*q6 + q7*q7;
#pragma unroll
        for (int o = 16; o > 0; o >>= 1) sq += __shfl_xor_sync(0xffffffffu, sq, o);

        uint32_t p0 = (q0 & 255) | ((q1 & 255) << 8) | ((q2 & 255) << 16) | ((uint32_t)(q3 & 255) << 24);
        uint32_t p1 = (q4 & 255) | ((q5 & 255) << 8) | ((q6 & 255) << 16) | ((uint32_t)(q7 & 255) << 24);
        ((uint32_t*)dst)[lane]      = p0;
        ((uint32_t*)dst)[lane + 32] = p1;

        if (lane == 0) {
            float n2 = KC * s * s * (float)sq;
            if (isA) g_wn2[w] = make_float4(al[w] * yt[w], n2, 2.0f * KC * s, 0.f);
            else     g_km2[w - N_TRAIN] = make_float2(n2, s);
        }
    }
}

// ---------------------------------------------------------------- main
// 8 warps in 2(row) x 4(col), warp tile 32x32 -> acc 32 regs -> 3 CTAs/SM.
extern "C" __global__ void __launch_bounds__(NTHREADS, 3) svm_main_kernel() {
    extern __shared__ char smem_raw[];
    const uint32_t s_base = smem_u32(smem_raw);
    const uint32_t sB_u   = s_base + OFF_B;
    const uint32_t sA_u[2] = { s_base + OFF_A0, s_base + OFF_A1 };
    float* sRed = (float*)(smem_raw + OFF_RED);

    const int tid  = threadIdx.x;
    const int lane = tid & 31;
    const int wid  = tid >> 5;
    const int wr   = wid >> 2;     // 0..1 : 32-row band
    const int wc   = wid & 3;      // 0..3 : 32-col band
    const int m0   = blockIdx.x * BN;
    const int n0   = blockIdx.y * ROWS_PER_SPLIT;

    // prologue: resident B + A stage 0
    cp_tile<BN>(sB_u, g_Bq + (size_t)m0 * D_DIM, tid);
    cp_tile<BM>(sA_u[0], g_Aq + (size_t)n0 * D_DIM, tid);
    asm volatile("cp.async.commit_group;");
    asm volatile("cp.async.wait_group 0;");
    __syncthreads();

    // ldmatrix per-lane bases (256B rows)
    const uint32_t aro  = (uint32_t)(wr * 32 + (lane & 15)) * 256;
    const uint32_t bro  = (uint32_t)(wc * 32 + (lane & 15)) * 256;
    const uint32_t csel = (uint32_t)(lane >> 4) & 1u;
    const uint32_t xr7  = (uint32_t)(lane & 7);
    const uint32_t bB   = sB_u + bro;

    const int colbase = m0 + wc * 32 + (lane & 3) * 2;   // j -> colbase + (j>>1)*8 + (j&1)

    float colacc[8];
#pragma unroll
    for (int j = 0; j < 8; j++) colacc[j] = 0.f;

    for (int i = 0; i < ITERS; i++) {
        const int s = i & 1;

        if (i + 1 < ITERS)
            cp_tile<BM>(sA_u[s ^ 1], g_Aq + (size_t)(n0 + (i + 1) * BM) * D_DIM, tid);
        asm volatile("cp.async.commit_group;");

        // ---- IMMA: 64x128x256 int8 tile, warp tile 32x32 ----
        int acc[2][4][4];
#pragma unroll
        for (int mf = 0; mf < 2; mf++)
#pragma unroll
            for (int ng = 0; ng < 4; ng++)
#pragma unroll
                for (int q = 0; q < 4; q++) acc[mf][ng][q] = 0;

        const uint32_t aB = sA_u[s] + aro;
#pragma unroll
        for (int ks = 0; ks < 8; ks++) {
            const uint32_t coff = (((2u * ks + csel) ^ xr7) << 4);
            uint32_t a[2][4], bq[2][4];
#pragma unroll
            for (int mf = 0; mf < 2; mf++)
                LDSM_X4(a[mf][0], a[mf][1], a[mf][2], a[mf][3], aB + mf * 4096 + coff);
#pragma unroll
            for (int p = 0; p < 2; p++)
                LDSM_X4(bq[p][0], bq[p][1], bq[p][2], bq[p][3], bB + p * 4096 + coff);
#pragma unroll
            for (int mf = 0; mf < 2; mf++)
#pragma unroll
                for (int ng = 0; ng < 4; ng++)
                    imma16832(acc[mf][ng], a[mf],
                              bq[ng >> 1][ng & 1], bq[ng >> 1][(ng & 1) + 2]);
        }

        // ---- epilogue: dequant + exp + weighted accumulate ----
#pragma unroll
        for (int mf = 0; mf < 2; mf++)
#pragma unroll
            for (int rh = 0; rh < 2; rh++) {
                float4 wn = __ldg(&g_wn2[n0 + i * BM + wr * 32 + mf * 16 + rh * 8 + (lane >> 2)]);
                const float negn = -wn.y;
#pragma unroll
                for (int ng = 0; ng < 4; ng++)
#pragma unroll
                    for (int h = 0; h < 2; h++) {
                        float2 cm = __ldg(&g_km2[colbase + ng * 8 + h]);
                        float df = (float)acc[mf][ng][rh * 2 + h];
                        float coef = wn.z * cm.y;            // 2*KC*s_a*s_b
                        float arg = fmaf(df, coef, negn) - cm.x;
                        arg = fminf(arg, 0.f);
                        float ev;
                        asm("ex2.approx.ftz.f32 %0, %1;" : "=f"(ev) : "f"(arg));
                        colacc[ng * 2 + h] = fmaf(ev, wn.x, colacc[ng * 2 + h]);
                    }
            }

        asm volatile("cp.async.wait_group 0;");
        __syncthreads();
    }

    // ---- deterministic column reduction ----
#pragma unroll
    for (int j = 0; j < 8; j++) {
        float v = colacc[j];
        v += __shfl_xor_sync(0xffffffffu, v, 4);
        v += __shfl_xor_sync(0xffffffffu, v, 8);
        v += __shfl_xor_sync(0xffffffffu, v, 16);
        colacc[j] = v;
    }
    if (lane < 4) {
#pragma unroll
        for (int j = 0; j < 8; j++) {
            int c = wc * 32 + (j >> 1) * 8 + lane * 2 + (j & 1);
            sRed[wr * BN + c] = colacc[j];
        }
    }
    __syncthreads();
    if (tid < BN)
        g_part[blockIdx.y][m0 + tid] = sRed[tid] + sRed[BN + tid];
}

// ---------------------------------------------------------------- reduce
__global__ void reduce_kernel(float* __restrict__ out) {
    int m = blockIdx.x * blockDim.x + threadIdx.x;
    if (m < M_PTS) {
        float s = 0.f;
#pragma unroll
        for (int r = 0; r < S_SPLIT; r++) s += g_part[r][m];
        out[m] = s;
    }
}

// ---------------------------------------------------------------- launch
extern "C" void kernel_launch(void* const* d_in, const int* in_sizes, int n_in,
                              void* d_out, int out_size) {
    const float* xt = (const float*)d_in[0];
    const float* yt = (const float*)d_in[1];
    const float* al = (const float*)d_in[2];
    const float* x  = (const float*)d_in[3];

    cudaFuncSetAttribute(svm_main_kernel,
                         cudaFuncAttributeMaxDynamicSharedMemorySize, SMEM_REQ);

    prep_kernel<<<(N_TRAIN + M_PTS) / 16, 256>>>(xt, yt, al, x);
    svm_main_kernel<<<dim3(M_PTS / BN, S_SPLIT), NTHREADS, SMEM_REQ>>>();
    reduce_kernel<<<(M_PTS + 255) / 256, 256>>>((float*)d_out);
}